// round 2
// baseline (speedup 1.0000x reference)
#include <cuda_runtime.h>
#include <mma.h>

using namespace nvcuda;

#define Bb 8
#define Cc 512
#define Nn 256
#define Tt 32
#define Pp 2048   // B*N
#define Mm 2048   // 4*C
#define Kk 512    // C

#define BM 128
#define BN 128
#define BK 32
#define LDA 36
#define LDB 132
#define LDZ 132

// scratch (device globals: no allocs allowed)
__device__ __align__(16) float g_Xt[(size_t)Tt * Kk * Pp];   // 134 MB: x transposed to [t][k][p]
__device__ __align__(16) float g_XP[(size_t)Tt * Mm * Pp];   // 512 MB: Wx @ x, rows interleaved m=4c+g
__device__ __align__(16) float g_H[2][Kk * Pp];              // hidden state ping-pong [k][p]
__device__ __align__(16) float g_Cell[Cc * Pp];              // cell state [c][p]

__global__ void init_state() {
    int i = blockIdx.x * blockDim.x + threadIdx.x;
    if (i < Kk * Pp) {
        g_H[0][i] = 0.f;
        g_H[1][i] = 0.f;
        g_Cell[i] = 0.f;
    }
}

// x (B,C,N,T) -> g_Xt[t][c][b*N + n]
__global__ void transpose_x(const float* __restrict__ x) {
    __shared__ float tile[32][33];
    int bid   = blockIdx.x;
    int ntile = bid & 7;          // Nn/32 = 8 tiles
    int bc    = bid >> 3;
    int c     = bc & (Cc - 1);
    int b     = bc >> 9;
    int tid = threadIdx.x;
    int tr = tid >> 5, tc = tid & 31;
    const float* src = x + ((size_t)(b * Cc + c) * Nn + ntile * 32) * Tt;
#pragma unroll
    for (int r0 = 0; r0 < 32; r0 += 8)
        tile[r0 + tr][tc] = src[(size_t)(r0 + tr) * Tt + tc];
    __syncthreads();
#pragma unroll
    for (int r0 = 0; r0 < 32; r0 += 8) {
        int t = r0 + tr;
        g_Xt[((size_t)t * Kk + c) * Pp + b * Nn + ntile * 32 + tc] = tile[tc][t];
    }
}

// 3xTF32 inner product core: acc += A*B with A,B split hi/lo
// (hi*hi + lo*hi + hi*lo; lo*lo term dropped — below fp32 lsb)

// XP[t][m][p] = sum_k Wx[g][c][k] * Xt[t][k][p],  m = 4c+g  (bias added in step kernel)
__global__ void xp_gemm(const float* __restrict__ Wx) {
    extern __shared__ float sm[];
    float* As = sm;                 // [BM][LDA]
    float* Bs = sm + BM * LDA;      // [BK][LDB]

    int colTile = blockIdx.x;       // 0..511  (t, p-tile)
    int mTile   = blockIdx.y;       // 0..15
    int t  = colTile >> 4;
    int p0 = (colTile & 15) * BN;
    int m0 = mTile * BM;

    int tid    = threadIdx.x;
    int warpId = tid >> 5;
    int wm = warpId & 3;            // 4 warps along M (32 rows each)
    int wn = warpId >> 2;           // 2 warps along N (64 cols each)

    wmma::fragment<wmma::accumulator, 16, 16, 8, float> acc[2][4];
#pragma unroll
    for (int i = 0; i < 2; i++)
#pragma unroll
        for (int j = 0; j < 4; j++) wmma::fill_fragment(acc[i][j], 0.f);

    const float* Bbase = g_Xt + (size_t)t * Kk * Pp + p0;

    for (int k0 = 0; k0 < Kk; k0 += BK) {
        // A tile: 128x32 of Wx, row m = 4c+g
#pragma unroll
        for (int it = 0; it < 4; it++) {
            int idx = tid + it * 256;       // 0..1023
            int row = idx >> 3;
            int q   = idx & 7;
            int m = m0 + row;
            int g = m & 3, c = m >> 2;
            float4 v = *reinterpret_cast<const float4*>(Wx + ((size_t)g * Cc + c) * Kk + k0 + q * 4);
            *reinterpret_cast<float4*>(As + row * LDA + q * 4) = v;
        }
        // B tile: 32x128 of Xt
#pragma unroll
        for (int it = 0; it < 4; it++) {
            int idx = tid + it * 256;
            int kk = idx >> 5;
            int q  = idx & 31;
            float4 v = *reinterpret_cast<const float4*>(Bbase + (size_t)(k0 + kk) * Pp + q * 4);
            *reinterpret_cast<float4*>(Bs + kk * LDB + q * 4) = v;
        }
        __syncthreads();
#pragma unroll
        for (int kk = 0; kk < BK; kk += 8) {
            wmma::fragment<wmma::matrix_a, 16, 16, 8, wmma::precision::tf32, wmma::row_major> afh[2], afl[2];
            wmma::fragment<wmma::matrix_b, 16, 16, 8, wmma::precision::tf32, wmma::row_major> bfh[4], bfl[4];
#pragma unroll
            for (int i = 0; i < 2; i++) {
                wmma::load_matrix_sync(afh[i], As + (wm * 32 + i * 16) * LDA + kk, LDA);
#pragma unroll
                for (int e = 0; e < afh[i].num_elements; e++) {
                    float v = afh[i].x[e];
                    float h = wmma::__float_to_tf32(v);
                    afh[i].x[e] = h;
                    afl[i].x[e] = wmma::__float_to_tf32(v - h);
                }
            }
#pragma unroll
            for (int j = 0; j < 4; j++) {
                wmma::load_matrix_sync(bfh[j], Bs + kk * LDB + wn * 64 + j * 16, LDB);
#pragma unroll
                for (int e = 0; e < bfh[j].num_elements; e++) {
                    float v = bfh[j].x[e];
                    float h = wmma::__float_to_tf32(v);
                    bfh[j].x[e] = h;
                    bfl[j].x[e] = wmma::__float_to_tf32(v - h);
                }
            }
#pragma unroll
            for (int i = 0; i < 2; i++)
#pragma unroll
                for (int j = 0; j < 4; j++) {
                    wmma::mma_sync(acc[i][j], afl[i], bfh[j], acc[i][j]);
                    wmma::mma_sync(acc[i][j], afh[i], bfl[j], acc[i][j]);
                    wmma::mma_sync(acc[i][j], afh[i], bfh[j], acc[i][j]);
                }
        }
        __syncthreads();
    }

    float* XPbase = g_XP + (size_t)t * Mm * Pp + (size_t)m0 * Pp + p0;
#pragma unroll
    for (int i = 0; i < 2; i++)
#pragma unroll
        for (int j = 0; j < 4; j++)
            wmma::store_matrix_sync(XPbase + (size_t)(wm * 32 + i * 16) * Pp + wn * 64 + j * 16,
                                    acc[i][j], Pp, wmma::mem_row_major);
}

// One LSTM step: Z = Wh_int @ H  (+XP_t +bias in epilogue), gates, cell update, H_next, out scatter.
__global__ void lstm_step(const float* __restrict__ Wh,
                          const float* __restrict__ bx,
                          const float* __restrict__ bh,
                          float* __restrict__ out, int t) {
    extern __shared__ float sm[];
    float* As = sm;
    float* Bs = sm + BM * LDA;
    float* Zs = sm;   // aliased; used only after the final __syncthreads

    int p0 = blockIdx.x * BN;   // 0..15 tiles
    int m0 = blockIdx.y * BM;   // 0..15 tiles

    int tid    = threadIdx.x;
    int warpId = tid >> 5;
    int wm = warpId & 3;
    int wn = warpId >> 2;

    const float* Hin = g_H[t & 1];
    float*       Hout = g_H[(t + 1) & 1];

    wmma::fragment<wmma::accumulator, 16, 16, 8, float> acc[2][4];
#pragma unroll
    for (int i = 0; i < 2; i++)
#pragma unroll
        for (int j = 0; j < 4; j++) wmma::fill_fragment(acc[i][j], 0.f);

    for (int k0 = 0; k0 < Kk; k0 += BK) {
#pragma unroll
        for (int it = 0; it < 4; it++) {
            int idx = tid + it * 256;
            int row = idx >> 3;
            int q   = idx & 7;
            int m = m0 + row;
            int g = m & 3, c = m >> 2;
            float4 v = *reinterpret_cast<const float4*>(Wh + ((size_t)g * Cc + c) * Kk + k0 + q * 4);
            *reinterpret_cast<float4*>(As + row * LDA + q * 4) = v;
        }
#pragma unroll
        for (int it = 0; it < 4; it++) {
            int idx = tid + it * 256;
            int kk = idx >> 5;
            int q  = idx & 31;
            float4 v = *reinterpret_cast<const float4*>(Hin + (size_t)(k0 + kk) * Pp + p0 + q * 4);
            *reinterpret_cast<float4*>(Bs + kk * LDB + q * 4) = v;
        }
        __syncthreads();
#pragma unroll
        for (int kk = 0; kk < BK; kk += 8) {
            wmma::fragment<wmma::matrix_a, 16, 16, 8, wmma::precision::tf32, wmma::row_major> afh[2], afl[2];
            wmma::fragment<wmma::matrix_b, 16, 16, 8, wmma::precision::tf32, wmma::row_major> bfh[4], bfl[4];
#pragma unroll
            for (int i = 0; i < 2; i++) {
                wmma::load_matrix_sync(afh[i], As + (wm * 32 + i * 16) * LDA + kk, LDA);
#pragma unroll
                for (int e = 0; e < afh[i].num_elements; e++) {
                    float v = afh[i].x[e];
                    float h = wmma::__float_to_tf32(v);
                    afh[i].x[e] = h;
                    afl[i].x[e] = wmma::__float_to_tf32(v - h);
                }
            }
#pragma unroll
            for (int j = 0; j < 4; j++) {
                wmma::load_matrix_sync(bfh[j], Bs + kk * LDB + wn * 64 + j * 16, LDB);
#pragma unroll
                for (int e = 0; e < bfh[j].num_elements; e++) {
                    float v = bfh[j].x[e];
                    float h = wmma::__float_to_tf32(v);
                    bfh[j].x[e] = h;
                    bfl[j].x[e] = wmma::__float_to_tf32(v - h);
                }
            }
#pragma unroll
            for (int i = 0; i < 2; i++)
#pragma unroll
                for (int j = 0; j < 4; j++) {
                    wmma::mma_sync(acc[i][j], afl[i], bfh[j], acc[i][j]);
                    wmma::mma_sync(acc[i][j], afh[i], bfl[j], acc[i][j]);
                    wmma::mma_sync(acc[i][j], afh[i], bfh[j], acc[i][j]);
                }
        }
        __syncthreads();
    }

    // stage Z tile to shared (gate quadruples are contiguous rows: m = 4c+g)
#pragma unroll
    for (int i = 0; i < 2; i++)
#pragma unroll
        for (int j = 0; j < 4; j++)
            wmma::store_matrix_sync(Zs + (wm * 32 + i * 16) * LDZ + wn * 64 + j * 16,
                                    acc[i][j], LDZ, wmma::mem_row_major);
    __syncthreads();

    const float* xpb = g_XP + (size_t)t * Mm * Pp;
#pragma unroll
    for (int it = 0; it < 16; it++) {
        int idx = tid + it * 256;        // 0..4095
        int cl = idx >> 7;               // channel within tile 0..31
        int pl = idx & 127;
        int c = (m0 >> 2) + cl;
        int p = p0 + pl;
        size_t xr = (size_t)(c * 4) * Pp + p;

        float zi = Zs[(4 * cl + 0) * LDZ + pl] + xpb[xr]            + bx[c]          + bh[c];
        float zf = Zs[(4 * cl + 1) * LDZ + pl] + xpb[xr + Pp]       + bx[Cc + c]     + bh[Cc + c];
        float zo = Zs[(4 * cl + 2) * LDZ + pl] + xpb[xr + 2 * Pp]   + bx[2 * Cc + c] + bh[2 * Cc + c];
        float zg = Zs[(4 * cl + 3) * LDZ + pl] + xpb[xr + 3 * Pp]   + bx[3 * Cc + c] + bh[3 * Cc + c];

        float ig = 1.f / (1.f + __expf(-zi));
        float fg = 1.f / (1.f + __expf(-zf));
        float og = 1.f / (1.f + __expf(-zo));
        float gg = tanhf(zg);

        float cp = g_Cell[c * Pp + p];
        float cn = fg * cp + ig * gg;
        g_Cell[c * Pp + p] = cn;
        float h = og * tanhf(cn);
        Hout[c * Pp + p] = h;

        int b = p >> 8, n = p & 255;
        out[(((size_t)b * Cc + c) * Nn + n) * Tt + t] = h;
    }
}

extern "C" void kernel_launch(void* const* d_in, const int* in_sizes, int n_in,
                              void* d_out, int out_size) {
    const float* x  = (const float*)d_in[0];
    const float* Wx = (const float*)d_in[1];
    const float* bx = (const float*)d_in[2];
    const float* Wh = (const float*)d_in[3];
    const float* bh = (const float*)d_in[4];
    float* out = (float*)d_out;

    const int smemGemm = (BM * LDA + BK * LDB) * sizeof(float);  // 35328 B
    const int smemStep = (BM * LDZ) * sizeof(float);             // 67584 B (>= staging size)
    cudaFuncSetAttribute(xp_gemm,   cudaFuncAttributeMaxDynamicSharedMemorySize, smemGemm);
    cudaFuncSetAttribute(lstm_step, cudaFuncAttributeMaxDynamicSharedMemorySize, smemStep);

    init_state<<<(Kk * Pp + 255) / 256, 256>>>();
    transpose_x<<<Bb * Cc * (Nn / 32), 256>>>(x);
    xp_gemm<<<dim3(512, 16), 256, smemGemm>>>(Wx);
    for (int t = 0; t < Tt; t++)
        lstm_step<<<dim3(16, 16), 256, smemStep>>>(Wh, bx, bh, out, t);
}

// round 4
// speedup vs baseline: 2.2464x; 2.2464x over previous
#include <cuda_runtime.h>
#include <cuda_bf16.h>
#include <mma.h>
#include <cstdint>

using namespace nvcuda;

#define Bb 8
#define Cc 512
#define Nn 256
#define Tt 32
#define Pp 2048   // B*N
#define Mm 2048   // 4*C
#define Kk 512    // C

#define BM 128
#define BN 128
#define BK 32
#define NKIT (Kk / BK)   // 16
#define LDA 40           // 32 + 8 pad (bf16 elems), 80B row stride
#define LDB 136          // 128 + 8 pad
#define LDZ 132          // fp32 staging pitch

#define SZ_A (BM * LDA)              // 5120 bf16
#define SZ_B (BK * LDB)              // 4352 bf16
#define BUF_ELEMS (2 * SZ_A + 2 * SZ_B)   // 18944 bf16 per buffer
#define SMEM_BYTES (2 * BUF_ELEMS * 2)    // 75776 B

// ------------ device scratch (no allocs allowed) ------------
__device__ __align__(16) __nv_bfloat16 g_XtH[(size_t)Tt * Kk * Pp]; // 67 MB
__device__ __align__(16) __nv_bfloat16 g_XtL[(size_t)Tt * Kk * Pp]; // 67 MB
__device__ __align__(16) float         g_XP[(size_t)Tt * Mm * Pp];  // 512 MB
__device__ __align__(16) __nv_bfloat16 g_WxH[Mm * Kk], g_WxL[Mm * Kk]; // rows m=4c+g
__device__ __align__(16) __nv_bfloat16 g_WhH[Mm * Kk], g_WhL[Mm * Kk];
__device__ __align__(16) __nv_bfloat16 g_HH[2][Kk * Pp], g_HL[2][Kk * Pp];
__device__ __align__(16) float         g_Cell[Cc * Pp];

// ------------ cp.async helpers ------------
__device__ __forceinline__ void cp16(void* dst, const void* src) {
    unsigned int d = (unsigned int)__cvta_generic_to_shared(dst);
    asm volatile("cp.async.cg.shared.global [%0], [%1], 16;\n" :: "r"(d), "l"(src));
}
#define CP_COMMIT() asm volatile("cp.async.commit_group;\n" ::)
#define CP_WAIT1()  asm volatile("cp.async.wait_group 1;\n" ::)
#define CP_WAIT0()  asm volatile("cp.async.wait_group 0;\n" ::)

__device__ __forceinline__ void bf16_split(float v, __nv_bfloat16& h, __nv_bfloat16& l) {
    h = __float2bfloat16(v);
    l = __float2bfloat16(v - __bfloat162float(h));
}

// ------------ setup kernels ------------
__global__ void init_state() {
    int i = blockIdx.x * blockDim.x + threadIdx.x;
    if (i < Kk * Pp) {
        __nv_bfloat16 z = __float2bfloat16(0.f);
        g_HH[0][i] = z; g_HH[1][i] = z;
        g_HL[0][i] = z; g_HL[1][i] = z;
        g_Cell[i] = 0.f;
    }
}

// Wx,Wh (4,C,C) fp32 -> bf16 hi/lo, rows interleaved m = 4c+g
__global__ void split_weights(const float* __restrict__ Wx, const float* __restrict__ Wh) {
    int idx = blockIdx.x * blockDim.x + threadIdx.x;   // 0 .. 4*C*C-1
    if (idx >= 4 * Cc * Cc) return;
    int g = idx >> 18;
    int rem = idx & ((1 << 18) - 1);
    int c = rem >> 9;
    int k = rem & 511;
    int m = (c << 2) | g;
    __nv_bfloat16 h, l;
    bf16_split(Wx[idx], h, l);
    g_WxH[m * Kk + k] = h; g_WxL[m * Kk + k] = l;
    bf16_split(Wh[idx], h, l);
    g_WhH[m * Kk + k] = h; g_WhL[m * Kk + k] = l;
}

// x (B,C,N,T) -> Xt hi/lo [t][c][b*N+n]
__global__ void transpose_split_x(const float* __restrict__ x) {
    __shared__ float tile[32][33];
    int bid   = blockIdx.x;
    int ntile = bid & 7;
    int bc    = bid >> 3;
    int c     = bc & (Cc - 1);
    int b     = bc >> 9;
    int tid = threadIdx.x;
    int tr = tid >> 5, tc = tid & 31;
    const float* src = x + ((size_t)(b * Cc + c) * Nn + ntile * 32) * Tt;
#pragma unroll
    for (int r0 = 0; r0 < 32; r0 += 8)
        tile[r0 + tr][tc] = src[(size_t)(r0 + tr) * Tt + tc];
    __syncthreads();
#pragma unroll
    for (int r0 = 0; r0 < 32; r0 += 8) {
        int t = r0 + tr;
        float v = tile[tc][t];
        __nv_bfloat16 h, l;
        bf16_split(v, h, l);
        size_t o = ((size_t)t * Kk + c) * Pp + b * Nn + ntile * 32 + tc;
        g_XtH[o] = h; g_XtL[o] = l;
    }
}

// ------------ shared GEMM core (3xBF16, double-buffered cp.async) ------------
struct AccTiles {
    wmma::fragment<wmma::accumulator, 16, 16, 16, float> a[2][4];
};

__device__ __forceinline__ void gemm_128x128_k512(
    const __nv_bfloat16* __restrict__ AH, const __nv_bfloat16* __restrict__ AL, // + m0*Kk applied
    const __nv_bfloat16* __restrict__ BH, const __nv_bfloat16* __restrict__ BL, // + p0 applied
    __nv_bfloat16* sm, int tid, int wm, int wn, AccTiles& acc)
{
#pragma unroll
    for (int i = 0; i < 2; i++)
#pragma unroll
        for (int j = 0; j < 4; j++) wmma::fill_fragment(acc.a[i][j], 0.f);

    auto load_tiles = [&](int buf, int k0) {
        __nv_bfloat16* base = sm + buf * BUF_ELEMS;
        __nv_bfloat16* asH = base;
        __nv_bfloat16* asL = base + SZ_A;
        __nv_bfloat16* bsH = base + 2 * SZ_A;
        __nv_bfloat16* bsL = base + 2 * SZ_A + SZ_B;
#pragma unroll
        for (int it = 0; it < 2; ++it) {
            int idx = tid + it * 256;
            int row = idx >> 2, q = idx & 3;
            cp16(asH + row * LDA + q * 8, AH + (size_t)row * Kk + k0 + q * 8);
            cp16(asL + row * LDA + q * 8, AL + (size_t)row * Kk + k0 + q * 8);
        }
#pragma unroll
        for (int it = 0; it < 2; ++it) {
            int idx = tid + it * 256;
            int kk = idx >> 4, q = idx & 15;
            cp16(bsH + kk * LDB + q * 8, BH + (size_t)(k0 + kk) * Pp + q * 8);
            cp16(bsL + kk * LDB + q * 8, BL + (size_t)(k0 + kk) * Pp + q * 8);
        }
        CP_COMMIT();
    };

    auto compute = [&](int buf) {
        __nv_bfloat16* base = sm + buf * BUF_ELEMS;
        __nv_bfloat16* asH = base;
        __nv_bfloat16* asL = base + SZ_A;
        __nv_bfloat16* bsH = base + 2 * SZ_A;
        __nv_bfloat16* bsL = base + 2 * SZ_A + SZ_B;
#pragma unroll
        for (int kk = 0; kk < BK; kk += 16) {
            wmma::fragment<wmma::matrix_a, 16, 16, 16, __nv_bfloat16, wmma::row_major> ah[2], al[2];
            wmma::fragment<wmma::matrix_b, 16, 16, 16, __nv_bfloat16, wmma::row_major> bh[4], bl[4];
#pragma unroll
            for (int i = 0; i < 2; i++) {
                wmma::load_matrix_sync(ah[i], asH + (wm * 32 + i * 16) * LDA + kk, LDA);
                wmma::load_matrix_sync(al[i], asL + (wm * 32 + i * 16) * LDA + kk, LDA);
            }
#pragma unroll
            for (int j = 0; j < 4; j++) {
                wmma::load_matrix_sync(bh[j], bsH + kk * LDB + wn * 64 + j * 16, LDB);
                wmma::load_matrix_sync(bl[j], bsL + kk * LDB + wn * 64 + j * 16, LDB);
            }
#pragma unroll
            for (int i = 0; i < 2; i++)
#pragma unroll
                for (int j = 0; j < 4; j++) {
                    wmma::mma_sync(acc.a[i][j], ah[i], bh[j], acc.a[i][j]);
                    wmma::mma_sync(acc.a[i][j], al[i], bh[j], acc.a[i][j]);
                    wmma::mma_sync(acc.a[i][j], ah[i], bl[j], acc.a[i][j]);
                }
        }
    };

    load_tiles(0, 0);
#pragma unroll 1
    for (int i = 0; i < NKIT; ++i) {
        if (i + 1 < NKIT) { load_tiles((i + 1) & 1, (i + 1) * BK); CP_WAIT1(); }
        else              { CP_WAIT0(); }
        __syncthreads();
        compute(i & 1);
        __syncthreads();
    }
}

// ------------ XP = Wx @ Xt ------------
__global__ __launch_bounds__(256) void xp_gemm() {
    extern __shared__ char smraw[];
    __nv_bfloat16* sm = reinterpret_cast<__nv_bfloat16*>(smraw);

    int colTile = blockIdx.x;          // t (5b) x ptile (4b)
    int t  = colTile >> 4;
    int p0 = (colTile & 15) * BN;
    int m0 = blockIdx.y * BM;

    int tid    = threadIdx.x;
    int warpId = tid >> 5;
    int wm = warpId & 3;
    int wn = warpId >> 2;

    AccTiles acc;
    gemm_128x128_k512(g_WxH + (size_t)m0 * Kk, g_WxL + (size_t)m0 * Kk,
                      g_XtH + (size_t)t * Kk * Pp + p0, g_XtL + (size_t)t * Kk * Pp + p0,
                      sm, tid, wm, wn, acc);

    float* XPbase = g_XP + (size_t)t * Mm * Pp + (size_t)m0 * Pp + p0;
#pragma unroll
    for (int i = 0; i < 2; i++)
#pragma unroll
        for (int j = 0; j < 4; j++)
            wmma::store_matrix_sync(XPbase + (size_t)(wm * 32 + i * 16) * Pp + wn * 64 + j * 16,
                                    acc.a[i][j], Pp, wmma::mem_row_major);
}

// ------------ one LSTM step ------------
__global__ __launch_bounds__(256) void lstm_step(const float* __restrict__ bx,
                                                 const float* __restrict__ bh,
                                                 float* __restrict__ out, int t) {
    extern __shared__ char smraw[];
    __nv_bfloat16* sm = reinterpret_cast<__nv_bfloat16*>(smraw);
    float* Zs = reinterpret_cast<float*>(smraw);   // alias, used after final sync

    int p0 = blockIdx.x * BN;
    int m0 = blockIdx.y * BM;

    int tid    = threadIdx.x;
    int warpId = tid >> 5;
    int wm = warpId & 3;
    int wn = warpId >> 2;

    AccTiles acc;
    gemm_128x128_k512(g_WhH + (size_t)m0 * Kk, g_WhL + (size_t)m0 * Kk,
                      g_HH[t & 1] + p0, g_HL[t & 1] + p0,
                      sm, tid, wm, wn, acc);

    // stage Z tile (gate quadruples contiguous: row m = 4c+g)
#pragma unroll
    for (int i = 0; i < 2; i++)
#pragma unroll
        for (int j = 0; j < 4; j++)
            wmma::store_matrix_sync(Zs + (wm * 32 + i * 16) * LDZ + wn * 64 + j * 16,
                                    acc.a[i][j], LDZ, wmma::mem_row_major);
    __syncthreads();

    __nv_bfloat16* HoutH = g_HH[(t + 1) & 1];
    __nv_bfloat16* HoutL = g_HL[(t + 1) & 1];
    const float* xpb = g_XP + (size_t)t * Mm * Pp;
#pragma unroll
    for (int it = 0; it < 16; it++) {
        int idx = tid + it * 256;        // 0..4095
        int cl = idx >> 7;               // channel within tile 0..31
        int pl = idx & 127;
        int c = (m0 >> 2) + cl;
        int p = p0 + pl;
        size_t xr = (size_t)(c * 4) * Pp + p;

        float zi = Zs[(4 * cl + 0) * LDZ + pl] + xpb[xr]          + bx[c]          + bh[c];
        float zf = Zs[(4 * cl + 1) * LDZ + pl] + xpb[xr + Pp]     + bx[Cc + c]     + bh[Cc + c];
        float zo = Zs[(4 * cl + 2) * LDZ + pl] + xpb[xr + 2 * Pp] + bx[2 * Cc + c] + bh[2 * Cc + c];
        float zg = Zs[(4 * cl + 3) * LDZ + pl] + xpb[xr + 3 * Pp] + bx[3 * Cc + c] + bh[3 * Cc + c];

        float ig = 1.f / (1.f + __expf(-zi));
        float fg = 1.f / (1.f + __expf(-zf));
        float og = 1.f / (1.f + __expf(-zo));
        float gg = tanhf(zg);

        float cp = g_Cell[c * Pp + p];
        float cn = fg * cp + ig * gg;
        g_Cell[c * Pp + p] = cn;
        float h = og * tanhf(cn);

        __nv_bfloat16 hh, hl;
        bf16_split(h, hh, hl);
        HoutH[c * Pp + p] = hh;
        HoutL[c * Pp + p] = hl;

        int b = p >> 8, n = p & 255;
        out[(((size_t)b * Cc + c) * Nn + n) * Tt + t] = h;
    }
}

extern "C" void kernel_launch(void* const* d_in, const int* in_sizes, int n_in,
                              void* d_out, int out_size) {
    const float* x  = (const float*)d_in[0];
    const float* Wx = (const float*)d_in[1];
    const float* bx = (const float*)d_in[2];
    const float* Wh = (const float*)d_in[3];
    const float* bh = (const float*)d_in[4];
    float* out = (float*)d_out;

    cudaFuncSetAttribute(xp_gemm,   cudaFuncAttributeMaxDynamicSharedMemorySize, SMEM_BYTES);
    cudaFuncSetAttribute(lstm_step, cudaFuncAttributeMaxDynamicSharedMemorySize, SMEM_BYTES);

    init_state<<<(Kk * Pp + 255) / 256, 256>>>();
    split_weights<<<(4 * Cc * Cc + 255) / 256, 256>>>(Wx, Wh);
    transpose_split_x<<<Bb * Cc * (Nn / 32), 256>>>(x);
    xp_gemm<<<dim3(512, 16), 256, SMEM_BYTES>>>();
    for (int t = 0; t < Tt; t++)
        lstm_step<<<dim3(16, 16), 256, SMEM_BYTES>>>(bx, bh, out, t);
}

// round 5
// speedup vs baseline: 3.1722x; 1.4121x over previous
#include <cuda_runtime.h>
#include <cuda_bf16.h>
#include <mma.h>
#include <cstdint>

using namespace nvcuda;

#define Bb 8
#define Cc 512
#define Nn 256
#define Tt 32
#define Pp 2048   // B*N
#define Mm 2048   // 4*C
#define Kk 512    // C

#define BM 128
#define BN 128
#define BK 32
#define NKIT (Kk / BK)   // 16
#define LDA 40           // 32 + 8 pad (bf16 elems)
#define LDB 136          // 128 + 8 pad
#define LDZ 132          // fp32 staging pitch

#define SZ_A (BM * LDA)              // 5120 bf16
#define SZ_B (BK * LDB)              // 4352 bf16
#define BUF_ELEMS (2 * SZ_A + 2 * SZ_B)   // 18944 bf16 per buffer
#define SMEM_BYTES (2 * BUF_ELEMS * 2)    // 75776 B

// ------------ device scratch (no allocs allowed) ------------
__device__ __align__(16) __nv_bfloat16 g_XtH[(size_t)Tt * Kk * Pp]; // 67 MB
__device__ __align__(16) __nv_bfloat16 g_XtL[(size_t)Tt * Kk * Pp]; // 67 MB
__device__ __align__(16) float         g_XP[(size_t)Tt * Mm * Pp];  // 512 MB
__device__ __align__(16) float         g_Hseq[(size_t)Tt * Cc * Pp]; // 134 MB: h history [t][c][p]
__device__ __align__(16) __nv_bfloat16 g_WxH[Mm * Kk], g_WxL[Mm * Kk]; // rows m=4c+g
__device__ __align__(16) __nv_bfloat16 g_WhH[Mm * Kk], g_WhL[Mm * Kk];
__device__ __align__(16) __nv_bfloat16 g_HH[2][Kk * Pp], g_HL[2][Kk * Pp];
__device__ __align__(16) float         g_Cell[Cc * Pp];

// ------------ cp.async helpers ------------
__device__ __forceinline__ void cp16(void* dst, const void* src) {
    unsigned int d = (unsigned int)__cvta_generic_to_shared(dst);
    asm volatile("cp.async.cg.shared.global [%0], [%1], 16;\n" :: "r"(d), "l"(src));
}
#define CP_COMMIT() asm volatile("cp.async.commit_group;\n" ::)
#define CP_WAIT1()  asm volatile("cp.async.wait_group 1;\n" ::)
#define CP_WAIT0()  asm volatile("cp.async.wait_group 0;\n" ::)

__device__ __forceinline__ void bf16_split(float v, __nv_bfloat16& h, __nv_bfloat16& l) {
    h = __float2bfloat16(v);
    l = __float2bfloat16(v - __bfloat162float(h));
}

// ------------ setup kernels ------------
__global__ void init_state() {
    int i = blockIdx.x * blockDim.x + threadIdx.x;
    if (i < Kk * Pp) {
        __nv_bfloat16 z = __float2bfloat16(0.f);
        g_HH[0][i] = z; g_HH[1][i] = z;
        g_HL[0][i] = z; g_HL[1][i] = z;
        g_Cell[i] = 0.f;
    }
}

// Wx,Wh (4,C,C) fp32 -> bf16 hi/lo, rows interleaved m = 4c+g
__global__ void split_weights(const float* __restrict__ Wx, const float* __restrict__ Wh) {
    int idx = blockIdx.x * blockDim.x + threadIdx.x;   // 0 .. 4*C*C-1
    if (idx >= 4 * Cc * Cc) return;
    int g = idx >> 18;
    int rem = idx & ((1 << 18) - 1);
    int c = rem >> 9;
    int k = rem & 511;
    int m = (c << 2) | g;
    __nv_bfloat16 h, l;
    bf16_split(Wx[idx], h, l);
    g_WxH[m * Kk + k] = h; g_WxL[m * Kk + k] = l;
    bf16_split(Wh[idx], h, l);
    g_WhH[m * Kk + k] = h; g_WhL[m * Kk + k] = l;
}

// x (B,C,N,T) -> Xt hi/lo [t][c][b*N+n]
__global__ void transpose_split_x(const float* __restrict__ x) {
    __shared__ float tile[32][33];
    int bid   = blockIdx.x;
    int ntile = bid & 7;
    int bc    = bid >> 3;
    int c     = bc & (Cc - 1);
    int b     = bc >> 9;
    int tid = threadIdx.x;
    int tr = tid >> 5, tc = tid & 31;
    const float* src = x + ((size_t)(b * Cc + c) * Nn + ntile * 32) * Tt;
#pragma unroll
    for (int r0 = 0; r0 < 32; r0 += 8)
        tile[r0 + tr][tc] = src[(size_t)(r0 + tr) * Tt + tc];
    __syncthreads();
#pragma unroll
    for (int r0 = 0; r0 < 32; r0 += 8) {
        int t = r0 + tr;
        float v = tile[tc][t];
        __nv_bfloat16 h, l;
        bf16_split(v, h, l);
        size_t o = ((size_t)t * Kk + c) * Pp + b * Nn + ntile * 32 + tc;
        g_XtH[o] = h; g_XtL[o] = l;
    }
}

// g_Hseq[t][c][b*N+n] -> out (B,C,N,T), both sides coalesced via smem tile
__global__ void transpose_out(float* __restrict__ out) {
    __shared__ float tile[32][33];
    int bid   = blockIdx.x;
    int ntile = bid & 7;
    int bc    = bid >> 3;
    int c     = bc & (Cc - 1);
    int b     = bc >> 9;
    int tid = threadIdx.x;
    int tr = tid >> 5, tc = tid & 31;   // tr: 0..7
#pragma unroll
    for (int r0 = 0; r0 < 32; r0 += 8) {
        int t = r0 + tr;
        tile[tc][t] = g_Hseq[((size_t)t * Cc + c) * Pp + b * Nn + ntile * 32 + tc];
    }
    __syncthreads();
    float* dst = out + ((size_t)(b * Cc + c) * Nn + ntile * 32) * Tt;
#pragma unroll
    for (int r0 = 0; r0 < 32; r0 += 8) {
        int n = r0 + tr;
        dst[(size_t)n * Tt + tc] = tile[n][tc];
    }
}

// ------------ shared GEMM core (3xBF16, double-buffered cp.async) ------------
struct AccTiles {
    wmma::fragment<wmma::accumulator, 16, 16, 16, float> a[2][4];
};

__device__ __forceinline__ void gemm_128x128_k512(
    const __nv_bfloat16* __restrict__ AH, const __nv_bfloat16* __restrict__ AL,
    const __nv_bfloat16* __restrict__ BH, const __nv_bfloat16* __restrict__ BL,
    __nv_bfloat16* sm, int tid, int wm, int wn, AccTiles& acc)
{
#pragma unroll
    for (int i = 0; i < 2; i++)
#pragma unroll
        for (int j = 0; j < 4; j++) wmma::fill_fragment(acc.a[i][j], 0.f);

    auto load_tiles = [&](int buf, int k0) {
        __nv_bfloat16* base = sm + buf * BUF_ELEMS;
        __nv_bfloat16* asH = base;
        __nv_bfloat16* asL = base + SZ_A;
        __nv_bfloat16* bsH = base + 2 * SZ_A;
        __nv_bfloat16* bsL = base + 2 * SZ_A + SZ_B;
#pragma unroll
        for (int it = 0; it < 2; ++it) {
            int idx = tid + it * 256;
            int row = idx >> 2, q = idx & 3;
            cp16(asH + row * LDA + q * 8, AH + (size_t)row * Kk + k0 + q * 8);
            cp16(asL + row * LDA + q * 8, AL + (size_t)row * Kk + k0 + q * 8);
        }
#pragma unroll
        for (int it = 0; it < 2; ++it) {
            int idx = tid + it * 256;
            int kk = idx >> 4, q = idx & 15;
            cp16(bsH + kk * LDB + q * 8, BH + (size_t)(k0 + kk) * Pp + q * 8);
            cp16(bsL + kk * LDB + q * 8, BL + (size_t)(k0 + kk) * Pp + q * 8);
        }
        CP_COMMIT();
    };

    auto compute = [&](int buf) {
        __nv_bfloat16* base = sm + buf * BUF_ELEMS;
        __nv_bfloat16* asH = base;
        __nv_bfloat16* asL = base + SZ_A;
        __nv_bfloat16* bsH = base + 2 * SZ_A;
        __nv_bfloat16* bsL = base + 2 * SZ_A + SZ_B;
#pragma unroll
        for (int kk = 0; kk < BK; kk += 16) {
            wmma::fragment<wmma::matrix_a, 16, 16, 16, __nv_bfloat16, wmma::row_major> ah[2], al[2];
#pragma unroll
            for (int i = 0; i < 2; i++) {
                wmma::load_matrix_sync(ah[i], asH + (wm * 32 + i * 16) * LDA + kk, LDA);
                wmma::load_matrix_sync(al[i], asL + (wm * 32 + i * 16) * LDA + kk, LDA);
            }
            // B fragments loaded per-j to keep register pressure low (2 CTAs/SM)
#pragma unroll
            for (int j = 0; j < 4; j++) {
                wmma::fragment<wmma::matrix_b, 16, 16, 16, __nv_bfloat16, wmma::row_major> bh, bl;
                wmma::load_matrix_sync(bh, bsH + kk * LDB + wn * 64 + j * 16, LDB);
                wmma::load_matrix_sync(bl, bsL + kk * LDB + wn * 64 + j * 16, LDB);
#pragma unroll
                for (int i = 0; i < 2; i++) {
                    wmma::mma_sync(acc.a[i][j], ah[i], bh, acc.a[i][j]);
                    wmma::mma_sync(acc.a[i][j], al[i], bh, acc.a[i][j]);
                    wmma::mma_sync(acc.a[i][j], ah[i], bl, acc.a[i][j]);
                }
            }
        }
    };

    load_tiles(0, 0);
#pragma unroll 1
    for (int i = 0; i < NKIT; ++i) {
        if (i + 1 < NKIT) { load_tiles((i + 1) & 1, (i + 1) * BK); CP_WAIT1(); }
        else              { CP_WAIT0(); }
        __syncthreads();
        compute(i & 1);
        __syncthreads();
    }
}

// ------------ XP = Wx @ Xt ------------
__global__ __launch_bounds__(256, 2) void xp_gemm() {
    extern __shared__ char smraw[];
    __nv_bfloat16* sm = reinterpret_cast<__nv_bfloat16*>(smraw);

    int colTile = blockIdx.x;
    int t  = colTile >> 4;
    int p0 = (colTile & 15) * BN;
    int m0 = blockIdx.y * BM;

    int tid    = threadIdx.x;
    int warpId = tid >> 5;
    int wm = warpId & 3;
    int wn = warpId >> 2;

    AccTiles acc;
    gemm_128x128_k512(g_WxH + (size_t)m0 * Kk, g_WxL + (size_t)m0 * Kk,
                      g_XtH + (size_t)t * Kk * Pp + p0, g_XtL + (size_t)t * Kk * Pp + p0,
                      sm, tid, wm, wn, acc);

    float* XPbase = g_XP + (size_t)t * Mm * Pp + (size_t)m0 * Pp + p0;
#pragma unroll
    for (int i = 0; i < 2; i++)
#pragma unroll
        for (int j = 0; j < 4; j++)
            wmma::store_matrix_sync(XPbase + (size_t)(wm * 32 + i * 16) * Pp + wn * 64 + j * 16,
                                    acc.a[i][j], Pp, wmma::mem_row_major);
}

// ------------ one LSTM step ------------
__global__ __launch_bounds__(256, 2) void lstm_step(const float* __restrict__ bx,
                                                    const float* __restrict__ bh,
                                                    int t) {
    extern __shared__ char smraw[];
    __nv_bfloat16* sm = reinterpret_cast<__nv_bfloat16*>(smraw);
    float* Zs = reinterpret_cast<float*>(smraw);   // alias, used after final sync

    int p0 = blockIdx.x * BN;
    int m0 = blockIdx.y * BM;

    int tid    = threadIdx.x;
    int warpId = tid >> 5;
    int wm = warpId & 3;
    int wn = warpId >> 2;

    AccTiles acc;
    gemm_128x128_k512(g_WhH + (size_t)m0 * Kk, g_WhL + (size_t)m0 * Kk,
                      g_HH[t & 1] + p0, g_HL[t & 1] + p0,
                      sm, tid, wm, wn, acc);

    // stage Z tile (gate quadruples contiguous: row m = 4c+g)
#pragma unroll
    for (int i = 0; i < 2; i++)
#pragma unroll
        for (int j = 0; j < 4; j++)
            wmma::store_matrix_sync(Zs + (wm * 32 + i * 16) * LDZ + wn * 64 + j * 16,
                                    acc.a[i][j], LDZ, wmma::mem_row_major);
    __syncthreads();

    __nv_bfloat16* HoutH = g_HH[(t + 1) & 1];
    __nv_bfloat16* HoutL = g_HL[(t + 1) & 1];
    const float* xpb = g_XP + (size_t)t * Mm * Pp;
#pragma unroll
    for (int it = 0; it < 16; it++) {
        int idx = tid + it * 256;        // 0..4095
        int cl = idx >> 7;
        int pl = idx & 127;
        int c = (m0 >> 2) + cl;
        int p = p0 + pl;
        size_t xr = (size_t)(c * 4) * Pp + p;

        float zi = Zs[(4 * cl + 0) * LDZ + pl] + xpb[xr]          + bx[c]          + bh[c];
        float zf = Zs[(4 * cl + 1) * LDZ + pl] + xpb[xr + Pp]     + bx[Cc + c]     + bh[Cc + c];
        float zo = Zs[(4 * cl + 2) * LDZ + pl] + xpb[xr + 2 * Pp] + bx[2 * Cc + c] + bh[2 * Cc + c];
        float zg = Zs[(4 * cl + 3) * LDZ + pl] + xpb[xr + 3 * Pp] + bx[3 * Cc + c] + bh[3 * Cc + c];

        float ig = 1.f / (1.f + __expf(-zi));
        float fg = 1.f / (1.f + __expf(-zf));
        float og = 1.f / (1.f + __expf(-zo));
        float gg = tanhf(zg);

        float cp = g_Cell[c * Pp + p];
        float cn = fg * cp + ig * gg;
        g_Cell[c * Pp + p] = cn;
        float h = og * tanhf(cn);

        __nv_bfloat16 hh, hl;
        bf16_split(h, hh, hl);
        HoutH[c * Pp + p] = hh;
        HoutL[c * Pp + p] = hl;

        g_Hseq[((size_t)t * Cc + c) * Pp + p] = h;   // coalesced; final transpose later
    }
}

extern "C" void kernel_launch(void* const* d_in, const int* in_sizes, int n_in,
                              void* d_out, int out_size) {
    const float* x  = (const float*)d_in[0];
    const float* Wx = (const float*)d_in[1];
    const float* bx = (const float*)d_in[2];
    const float* Wh = (const float*)d_in[3];
    const float* bh = (const float*)d_in[4];
    float* out = (float*)d_out;

    cudaFuncSetAttribute(xp_gemm,   cudaFuncAttributeMaxDynamicSharedMemorySize, SMEM_BYTES);
    cudaFuncSetAttribute(lstm_step, cudaFuncAttributeMaxDynamicSharedMemorySize, SMEM_BYTES);

    init_state<<<(Kk * Pp + 255) / 256, 256>>>();
    split_weights<<<(4 * Cc * Cc + 255) / 256, 256>>>(Wx, Wh);
    transpose_split_x<<<Bb * Cc * (Nn / 32), 256>>>(x);
    xp_gemm<<<dim3(512, 16), 256, SMEM_BYTES>>>();
    for (int t = 0; t < Tt; t++)
        lstm_step<<<dim3(16, 16), 256, SMEM_BYTES>>>(bx, bh, t);
    transpose_out<<<Bb * Cc * (Nn / 32), 256>>>(out);
}